// round 16
// baseline (speedup 1.0000x reference)
#include <cuda_runtime.h>
#include <cuda_fp16.h>
#include <cstdint>

// ---------------------------------------------------------------------------
// Problem constants
// ---------------------------------------------------------------------------
#define DIN_   2048
#define NQ_    4096
#define NK_    1024
#define NTOT_  5120
#define DHEAD_ 128
#define NHEAD_ 8
#define NGROUP_ 4
#define SINK_  16
#define SMAX_  32768
#define NCHUNK 4

__device__ __half g_qh[(size_t)SMAX_ * NQ_];     // 256 MB fp16 q scratch
__device__ __half g_kh[(size_t)SMAX_ * NK_];     // 64 MB  fp16 k scratch
__device__ __half g_hbuf[(size_t)SMAX_ * DIN_];  // 128 MB fp16 hidden
__device__ __half g_wbuf[(size_t)NTOT_ * DIN_];  // 20 MB  fp16 [Wq;Wk]

// ---------------------------------------------------------------------------
// fp32 -> fp16 conversion (RN), vectorized
// ---------------------------------------------------------------------------
__global__ void __launch_bounds__(256) cvt_fp16(const float4* __restrict__ src,
                                                uint2* __restrict__ dst, int n4)
{
    int i = blockIdx.x * blockDim.x + threadIdx.x;
    if (i < n4) {
        float4 v = src[i];
        __half2 h0 = __floats2half2_rn(v.x, v.y);
        __half2 h1 = __floats2half2_rn(v.z, v.w);
        uint2 o;
        o.x = *reinterpret_cast<uint32_t*>(&h0);
        o.y = *reinterpret_cast<uint32_t*>(&h1);
        dst[i] = o;
    }
}

// ---------------------------------------------------------------------------
// GEMM (unchanged): mma.sync m16n8k16 fp16, BM=128 BN=128 BK=64,
// 3-stage ring (96 KB), 2 CTAs/SM, warp tile 64x32.
// ---------------------------------------------------------------------------
#define BM 128
#define BN 128
#define BK 64
#define NSTAGE 3
#define A_BYTES (128 * 128)
#define B_BYTES (128 * 128)
#define SLOT_BYTES (A_BYTES + B_BYTES)
#define SMEM_TOTAL (NSTAGE * SLOT_BYTES)   // 96 KB

__device__ __forceinline__ uint32_t smem_to_u32(const void* p) {
    uint32_t a;
    asm("{ .reg .u64 t; cvta.to.shared.u64 t, %1; cvt.u32.u64 %0, t; }" : "=r"(a) : "l"(p));
    return a;
}

__device__ __forceinline__ void cp16s(uint32_t dst, const __half* src) {
    asm volatile("cp.async.cg.shared.global [%0], [%1], 16;\n" :: "r"(dst), "l"(src));
}

__device__ __forceinline__ void ldsm_x4(uint32_t& r0, uint32_t& r1, uint32_t& r2,
                                        uint32_t& r3, uint32_t addr) {
    asm volatile("ldmatrix.sync.aligned.m8n8.x4.shared.b16 {%0,%1,%2,%3}, [%4];"
                 : "=r"(r0), "=r"(r1), "=r"(r2), "=r"(r3) : "r"(addr));
}

__device__ __forceinline__ void mma_f16(float c[4], const uint32_t a[4],
                                        const uint32_t b0, const uint32_t b1) {
    asm volatile(
        "mma.sync.aligned.m16n8k16.row.col.f32.f16.f16.f32 "
        "{%0,%1,%2,%3}, {%4,%5,%6,%7}, {%8,%9}, {%0,%1,%2,%3};\n"
        : "+f"(c[0]), "+f"(c[1]), "+f"(c[2]), "+f"(c[3])
        : "r"(a[0]), "r"(a[1]), "r"(a[2]), "r"(a[3]), "r"(b0), "r"(b1));
}

__device__ __forceinline__ uint32_t swz(int row, int chunk) {
    return (uint32_t)(row * 128 + ((chunk ^ (row & 7)) << 4));
}

__global__ void __launch_bounds__(256, 2) gemm_qk(const float* __restrict__ bq,
                                                  int m_base)
{
    extern __shared__ char smem[];
    const uint32_t sbase = smem_to_u32(smem);
    const int tid = threadIdx.x;
    const int lane = tid & 31, wid = tid >> 5;
    const int wm = wid >> 2, wn = wid & 3;
    const int gid = lane >> 2, tig = lane & 3;

    const int n0 = blockIdx.x * BN;
    const int m0 = m_base + blockIdx.y * BM;
    const bool isq = (n0 < NQ_);
    const __half* wrow = g_wbuf + (size_t)n0 * DIN_;
    const __half* arow = g_hbuf + (size_t)m0 * DIN_;

    float acc[4][4][4];
#pragma unroll
    for (int a = 0; a < 4; a++)
#pragma unroll
        for (int b = 0; b < 4; b++)
#pragma unroll
            for (int c = 0; c < 4; c++) acc[a][b][c] = 0.f;

    const int arow_l   = wm * 64 + (lane & 15);
    const int achunk_l = lane >> 4;
    const int brow_l   = wn * 32 + (lane & 7) + ((lane & 16) >> 1);
    const int bchunk_l = (lane >> 3) & 1;

    auto load_stage = [&](int s) {
        const uint32_t slot = sbase + (uint32_t)(s % NSTAGE) * SLOT_BYTES;
        const int k0 = s * BK;
#pragma unroll
        for (int i = 0; i < 4; i++) {
            int id = tid + i * 256;
            int r = id >> 3, c = id & 7;
            cp16s(slot + swz(r, c), arow + (size_t)r * DIN_ + k0 + c * 8);
        }
#pragma unroll
        for (int i = 0; i < 4; i++) {
            int id = tid + i * 256;
            int r = id >> 3, c = id & 7;
            cp16s(slot + A_BYTES + swz(r, c), wrow + (size_t)r * DIN_ + k0 + c * 8);
        }
        asm volatile("cp.async.commit_group;\n");
    };

    load_stage(0);
    load_stage(1);

    const int NSTEPS = DIN_ / BK;  // 32
    for (int s = 0; s < NSTEPS; s++) {
        if (s < NSTEPS - 1) asm volatile("cp.async.wait_group 1;\n" ::: "memory");
        else                asm volatile("cp.async.wait_group 0;\n" ::: "memory");
        __syncthreads();

        const uint32_t slot = sbase + (uint32_t)(s % NSTAGE) * SLOT_BYTES;
#pragma unroll
        for (int ks = 0; ks < 4; ks++) {
            uint32_t af[4][4], bf[2][4];
#pragma unroll
            for (int tm = 0; tm < 4; tm++)
                ldsm_x4(af[tm][0], af[tm][1], af[tm][2], af[tm][3],
                        slot + swz(arow_l + tm * 16, 2 * ks + achunk_l));
#pragma unroll
            for (int np = 0; np < 2; np++)
                ldsm_x4(bf[np][0], bf[np][1], bf[np][2], bf[np][3],
                        slot + A_BYTES + swz(brow_l + np * 16, 2 * ks + bchunk_l));
#pragma unroll
            for (int tm = 0; tm < 4; tm++)
#pragma unroll
                for (int np = 0; np < 2; np++) {
                    mma_f16(acc[tm][2 * np],     af[tm], bf[np][0], bf[np][1]);
                    mma_f16(acc[tm][2 * np + 1], af[tm], bf[np][2], bf[np][3]);
                }
        }

        if (s + 2 < NSTEPS) load_stage(s + 2);
    }

    float bq0[4], bq1[4];
#pragma unroll
    for (int tn = 0; tn < 4; tn++) {
        int col = n0 + wn * 32 + tn * 8 + 2 * tig;
        bq0[tn] = isq ? __ldg(bq + col) : 0.f;
        bq1[tn] = isq ? __ldg(bq + col + 1) : 0.f;
    }
    __half* obase = isq ? g_qh : g_kh;
    const int ld = isq ? NQ_ : NK_;
    const int cb = isq ? n0 : (n0 - NQ_);

#pragma unroll
    for (int tm = 0; tm < 4; tm++) {
#pragma unroll
        for (int tn = 0; tn < 4; tn++) {
            int r = m0 + wm * 64 + tm * 16 + gid;
            int c = cb + wn * 32 + tn * 8 + 2 * tig;
            __half2 v0 = __floats2half2_rn(acc[tm][tn][0] + bq0[tn], acc[tm][tn][1] + bq1[tn]);
            __half2 v1 = __floats2half2_rn(acc[tm][tn][2] + bq0[tn], acc[tm][tn][3] + bq1[tn]);
            *reinterpret_cast<__half2*>(obase + (size_t)r * ld + c) = v0;
            *reinterpret_cast<__half2*>(obase + (size_t)(r + 8) * ld + c) = v1;
        }
    }
}

// ---------------------------------------------------------------------------
// Epilogue v4: token-pair ILP; the 16-value sink butterfly now runs ONCE on
// half2-packed pairs (token0 in .x, token1 in .y) — halves the butterfly shfl
// count. Sink partials have magnitude ~0.2 so fp16 reduction error is ~2e-5
// on the exp argument. qss/dtt (large magnitude) stay fp32.
// ---------------------------------------------------------------------------
#define ETOK 32
#define EQB (NQ_ * 2)
#define EKB (NK_ * 2)
#define ETOKB (EQB + EKB)
#define EPSLOT (2 * ETOKB)
#define EPI_SMEM (3 * EPSLOT)          // 61440 B

__device__ __forceinline__ void wsum2(float& a, float& b) {
#pragma unroll
    for (int m = 16; m >= 1; m >>= 1) {
        a += __shfl_xor_sync(0xffffffffu, a, m);
        b += __shfl_xor_sync(0xffffffffu, b, m);
    }
}

__device__ __forceinline__ __half2 h2shfl_xor(__half2 v, int m) {
    uint32_t u = *reinterpret_cast<uint32_t*>(&v);
    u = __shfl_xor_sync(0xffffffffu, u, m);
    return *reinterpret_cast<__half2*>(&u);
}

__device__ __forceinline__ void ld4h_s(float o[4], uint32_t a) {
    uint32_t r0, r1;
    asm volatile("ld.shared.v2.b32 {%0,%1}, [%2];" : "=r"(r0), "=r"(r1) : "r"(a));
    __half2 h0 = *reinterpret_cast<__half2*>(&r0);
    __half2 h1 = *reinterpret_cast<__half2*>(&r1);
    float2 f0 = __half22float2(h0), f1 = __half22float2(h1);
    o[0] = f0.x; o[1] = f0.y; o[2] = f1.x; o[3] = f1.y;
}

__global__ void __launch_bounds__(256) epilogue_kernel(
    float* __restrict__ out, const float* __restrict__ bvec,
    const float* __restrict__ k_base, const float* __restrict__ qw,
    const float* __restrict__ kw, int nseq, int tok_base)
{
    extern __shared__ char esm[];
    const uint32_t sbase = smem_to_u32(esm);
    const int tid = threadIdx.x;
    const int lane = tid & 31;
    const int h = tid >> 5;
    const float inv_d = 0.08838834764831845f;
    const int tok0 = tok_base + blockIdx.x * ETOK;

    float qwr[4], kwr[4];
#pragma unroll
    for (int j = 0; j < 4; j++) {
        qwr[j] = qw[4 * lane + j];
        kwr[j] = kw[4 * lane + j];
    }
    __half2 kbq2[SINK_][2];
#pragma unroll
    for (int t = 0; t < SINK_; t++) {
        const float* kb = k_base + (size_t)(h * SINK_ + t) * DHEAD_ + 4 * lane;
        kbq2[t][0] = __floats2half2_rn(kb[0] * qwr[0], kb[1] * qwr[1]);
        kbq2[t][1] = __floats2half2_rn(kb[2] * qwr[2], kb[3] * qwr[3]);
    }

    float bb[4];
#pragma unroll
    for (int g = 0; g < NGROUP_; g++) bb[g] = bvec[h * NGROUP_ + g];

    const bool up16 = (lane & 16) != 0;
    const bool up8  = (lane & 8) != 0;
    const bool up4  = (lane & 4) != 0;
    const bool up2  = (lane & 2) != 0;

    auto load_pair = [&](int p) {
        const uint32_t slot = sbase + (uint32_t)(p % 3) * EPSLOT;
#pragma unroll
        for (int tt = 0; tt < 2; tt++) {
            const int s = tok0 + 2 * p + tt;
            const uint32_t tb = slot + (uint32_t)tt * ETOKB;
            const __half* qsrc = g_qh + (size_t)s * NQ_;
            const __half* ksrc = g_kh + (size_t)s * NK_;
            cp16s(tb + (uint32_t)tid * 16, qsrc + tid * 8);
            cp16s(tb + (uint32_t)(tid + 256) * 16, qsrc + (tid + 256) * 8);
            if (tid < 128) cp16s(tb + EQB + (uint32_t)tid * 16, ksrc + tid * 8);
        }
        asm volatile("cp.async.commit_group;\n");
    };

    load_pair(0);
    load_pair(1);

    const int NPAIR = ETOK / 2;   // 16
    for (int p = 0; p < NPAIR; p++) {
        if (p < NPAIR - 1) asm volatile("cp.async.wait_group 1;\n" ::: "memory");
        else               asm volatile("cp.async.wait_group 0;\n" ::: "memory");
        __syncthreads();

        if (p + 2 < NPAIR) load_pair(p + 2);

        const uint32_t slot = sbase + (uint32_t)(p % 3) * EPSLOT;

        float kd[2][4], kdq[2][4], kss[2];
#pragma unroll
        for (int tt = 0; tt < 2; tt++) {
            ld4h_s(kd[tt], slot + (uint32_t)tt * ETOKB + EQB + (uint32_t)(h * DHEAD_ + 4 * lane) * 2);
            kss[tt] = kd[tt][0]*kd[tt][0] + kd[tt][1]*kd[tt][1]
                    + kd[tt][2]*kd[tt][2] + kd[tt][3]*kd[tt][3];
#pragma unroll
            for (int j = 0; j < 4; j++) kdq[tt][j] = kd[tt][j] * kwr[j] * qwr[j];
        }
        wsum2(kss[0], kss[1]);
        float rk[2];
#pragma unroll
        for (int tt = 0; tt < 2; tt++)
            rk[tt] = rsqrtf(kss[tt] * (1.0f / DHEAD_) + 1e-6f);

        float accg[2] = {0.f, 0.f};
#pragma unroll
        for (int g = 0; g < NGROUP_; g++) {
            float qd[2][4], qss[2], dtt[2];
#pragma unroll
            for (int tt = 0; tt < 2; tt++) {
                ld4h_s(qd[tt], slot + (uint32_t)tt * ETOKB
                       + (uint32_t)(h * (NGROUP_ * DHEAD_) + g * DHEAD_ + 4 * lane) * 2);
                qss[tt] = qd[tt][0]*qd[tt][0] + qd[tt][1]*qd[tt][1]
                        + qd[tt][2]*qd[tt][2] + qd[tt][3]*qd[tt][3];
                dtt[tt] = kdq[tt][0]*qd[tt][0] + kdq[tt][1]*qd[tt][1]
                        + kdq[tt][2]*qd[tt][2] + kdq[tt][3]*qd[tt][3];
            }

            // sink partials, packed: .x = token0, .y = token1
            __half2 ph[SINK_];
#pragma unroll
            for (int t = 0; t < SINK_; t++) {
                float2 c0 = __half22float2(kbq2[t][0]);
                float2 c1 = __half22float2(kbq2[t][1]);
                float p0 = c0.x*qd[0][0] + c0.y*qd[0][1] + c1.x*qd[0][2] + c1.y*qd[0][3];
                float p1 = c0.x*qd[1][0] + c0.y*qd[1][1] + c1.x*qd[1][2] + c1.y*qd[1][3];
                ph[t] = __floats2half2_rn(p0, p1);
            }

            wsum2(qss[0], qss[1]);
            wsum2(dtt[0], dtt[1]);

            // SINGLE packed butterfly: 16 half2 vals/lane -> 1 half2/lane
            __half2 v8[8];
#pragma unroll
            for (int ii = 0; ii < 8; ii++) {
                __half2 sd  = up16 ? ph[ii] : ph[8 + ii];
                __half2 kp2 = up16 ? ph[8 + ii] : ph[ii];
                v8[ii] = __hadd2(kp2, h2shfl_xor(sd, 16));
            }
            __half2 v4[4];
#pragma unroll
            for (int ii = 0; ii < 4; ii++) {
                __half2 sd  = up8 ? v8[ii] : v8[4 + ii];
                __half2 kp2 = up8 ? v8[4 + ii] : v8[ii];
                v4[ii] = __hadd2(kp2, h2shfl_xor(sd, 8));
            }
            __half2 v2[2];
#pragma unroll
            for (int ii = 0; ii < 2; ii++) {
                __half2 sd  = up4 ? v4[ii] : v4[2 + ii];
                __half2 kp2 = up4 ? v4[2 + ii] : v4[ii];
                v2[ii] = __hadd2(kp2, h2shfl_xor(sd, 4));
            }
            __half2 sd1 = up2 ? v2[0] : v2[1];
            __half2 kp1 = up2 ? v2[1] : v2[0];
            __half2 v1 = __hadd2(kp1, h2shfl_xor(sd1, 2));
            __half2 S2 = __hadd2(v1, h2shfl_xor(v1, 1));
            float2 Sf = __half22float2(S2);
            float S[2] = {Sf.x, Sf.y};

            float e[2];
#pragma unroll
            for (int tt = 0; tt < 2; tt++) {
                float rq = rsqrtf(qss[tt] * (1.0f / DHEAD_) + 1e-6f);
                float logit = rk[tt] * rq * dtt[tt] * inv_d + 2.f * bb[g];
                e[tt] = __expf(rq * S[tt] * inv_d - logit);
            }
            wsum2(e[0], e[1]);
#pragma unroll
            for (int tt = 0; tt < 2; tt++)
                accg[tt] += 1.f / (1.f + 0.5f * e[tt]);
        }
        if (lane == 0) {
#pragma unroll
            for (int tt = 0; tt < 2; tt++)
                out[(size_t)h * nseq + tok0 + 2 * p + tt] = 0.25f * accg[tt];
        }
    }
}

// ---------------------------------------------------------------------------
// Launch: R13 topology (best measured) — equal chunks, single gemm stream,
// chunked hidden cvt on s2, epilogue chunks on high-priority s1.
// ---------------------------------------------------------------------------
extern "C" void kernel_launch(void* const* d_in, const int* in_sizes, int n_in,
                              void* d_out, int out_size)
{
    const float* hidden = (const float*)d_in[0];
    const float* Wq     = (const float*)d_in[1];
    const float* bq     = (const float*)d_in[2];
    const float* Wk     = (const float*)d_in[3];
    const float* qw     = (const float*)d_in[4];
    const float* kw     = (const float*)d_in[5];
    const float* bvec   = (const float*)d_in[6];
    const float* kbase  = (const float*)d_in[7];

    const int nseq = in_sizes[0] / DIN_;
    const int chunk = nseq / NCHUNK;

    static cudaStream_t s1 = nullptr, s2 = nullptr;
    static cudaEvent_t evRoot, evW, evE;
    static cudaEvent_t evG[NCHUNK], evC[NCHUNK];
    if (s1 == nullptr) {
        int lo, hi;
        cudaDeviceGetStreamPriorityRange(&lo, &hi);
        cudaStreamCreateWithPriority(&s1, cudaStreamNonBlocking, hi);
        cudaStreamCreateWithFlags(&s2, cudaStreamNonBlocking);
        cudaEventCreateWithFlags(&evRoot, cudaEventDisableTiming);
        cudaEventCreateWithFlags(&evW, cudaEventDisableTiming);
        cudaEventCreateWithFlags(&evE, cudaEventDisableTiming);
        for (int c = 0; c < NCHUNK; c++) {
            cudaEventCreateWithFlags(&evG[c], cudaEventDisableTiming);
            cudaEventCreateWithFlags(&evC[c], cudaEventDisableTiming);
        }
        cudaFuncSetAttribute(gemm_qk, cudaFuncAttributeMaxDynamicSharedMemorySize, SMEM_TOTAL);
        cudaFuncSetAttribute(epilogue_kernel, cudaFuncAttributeMaxDynamicSharedMemorySize, EPI_SMEM);
    }

    __half* hb;  cudaGetSymbolAddress((void**)&hb, g_hbuf);
    __half* wb;  cudaGetSymbolAddress((void**)&wb, g_wbuf);

    // fork
    cudaEventRecord(evRoot, 0);
    cudaStreamWaitEvent(s1, evRoot, 0);
    cudaStreamWaitEvent(s2, evRoot, 0);

    // s1: weight conversions
    {
        int n4 = NQ_ * DIN_ / 4;
        cvt_fp16<<<(n4 + 255) / 256, 256, 0, s1>>>((const float4*)Wq, (uint2*)wb, n4);
        n4 = NK_ * DIN_ / 4;
        cvt_fp16<<<(n4 + 255) / 256, 256, 0, s1>>>((const float4*)Wk,
                                                   (uint2*)(wb + (size_t)NQ_ * DIN_), n4);
        cudaEventRecord(evW, s1);
    }

    // s2: hidden conversion, chunk-wise
    {
        const int c4 = chunk * DIN_ / 4;
        for (int c = 0; c < NCHUNK; c++) {
            cvt_fp16<<<(c4 + 255) / 256, 256, 0, s2>>>(
                (const float4*)hidden + (size_t)c * c4,
                (uint2*)hb + (size_t)c * c4, c4);
            cudaEventRecord(evC[c], s2);
        }
    }

    // s0: gemm chunks; s1: epilogue chunks
    cudaStreamWaitEvent(0, evW, 0);
    dim3 ggrid(NTOT_ / BN, chunk / BM);   // 40 x 64 per chunk
    for (int c = 0; c < NCHUNK; c++) {
        cudaStreamWaitEvent(0, evC[c], 0);
        gemm_qk<<<ggrid, 256, SMEM_TOTAL>>>(bq, c * chunk);
        cudaEventRecord(evG[c], 0);
        cudaStreamWaitEvent(s1, evG[c], 0);
        epilogue_kernel<<<chunk / ETOK, 256, EPI_SMEM, s1>>>(
            (float*)d_out, bvec, kbase, qw, kw, nseq, c * chunk);
    }

    // join
    cudaEventRecord(evE, s1);
    cudaStreamWaitEvent(0, evE, 0);
}

// round 17
// speedup vs baseline: 1.1968x; 1.1968x over previous
#include <cuda_runtime.h>
#include <cuda_fp16.h>
#include <cstdint>

// ---------------------------------------------------------------------------
// Problem constants
// ---------------------------------------------------------------------------
#define DIN_   2048
#define NQ_    4096
#define NK_    1024
#define NTOT_  5120
#define DHEAD_ 128
#define NHEAD_ 8
#define NGROUP_ 4
#define SINK_  16
#define SMAX_  32768
#define NCHUNK 4

__device__ __half g_qh[(size_t)SMAX_ * NQ_];     // 256 MB fp16 q scratch
__device__ __half g_kh[(size_t)SMAX_ * NK_];     // 64 MB  fp16 k scratch
__device__ __half g_hbuf[(size_t)SMAX_ * DIN_];  // 128 MB fp16 hidden
__device__ __half g_wbuf[(size_t)NTOT_ * DIN_];  // 20 MB  fp16 [Wq;Wk]

// ---------------------------------------------------------------------------
// fp32 -> fp16 conversion (RN), vectorized
// ---------------------------------------------------------------------------
__global__ void __launch_bounds__(256) cvt_fp16(const float4* __restrict__ src,
                                                uint2* __restrict__ dst, int n4)
{
    int i = blockIdx.x * blockDim.x + threadIdx.x;
    if (i < n4) {
        float4 v = src[i];
        __half2 h0 = __floats2half2_rn(v.x, v.y);
        __half2 h1 = __floats2half2_rn(v.z, v.w);
        uint2 o;
        o.x = *reinterpret_cast<uint32_t*>(&h0);
        o.y = *reinterpret_cast<uint32_t*>(&h1);
        dst[i] = o;
    }
}

// ---------------------------------------------------------------------------
// GEMM (unchanged): mma.sync m16n8k16 fp16, BM=128 BN=128 BK=64,
// 3-stage ring (96 KB), 2 CTAs/SM, warp tile 64x32.
// ---------------------------------------------------------------------------
#define BM 128
#define BN 128
#define BK 64
#define NSTAGE 3
#define A_BYTES (128 * 128)
#define B_BYTES (128 * 128)
#define SLOT_BYTES (A_BYTES + B_BYTES)
#define SMEM_TOTAL (NSTAGE * SLOT_BYTES)   // 96 KB

__device__ __forceinline__ uint32_t smem_to_u32(const void* p) {
    uint32_t a;
    asm("{ .reg .u64 t; cvta.to.shared.u64 t, %1; cvt.u32.u64 %0, t; }" : "=r"(a) : "l"(p));
    return a;
}

__device__ __forceinline__ void cp16s(uint32_t dst, const __half* src) {
    asm volatile("cp.async.cg.shared.global [%0], [%1], 16;\n" :: "r"(dst), "l"(src));
}

__device__ __forceinline__ void ldsm_x4(uint32_t& r0, uint32_t& r1, uint32_t& r2,
                                        uint32_t& r3, uint32_t addr) {
    asm volatile("ldmatrix.sync.aligned.m8n8.x4.shared.b16 {%0,%1,%2,%3}, [%4];"
                 : "=r"(r0), "=r"(r1), "=r"(r2), "=r"(r3) : "r"(addr));
}

__device__ __forceinline__ void mma_f16(float c[4], const uint32_t a[4],
                                        const uint32_t b0, const uint32_t b1) {
    asm volatile(
        "mma.sync.aligned.m16n8k16.row.col.f32.f16.f16.f32 "
        "{%0,%1,%2,%3}, {%4,%5,%6,%7}, {%8,%9}, {%0,%1,%2,%3};\n"
        : "+f"(c[0]), "+f"(c[1]), "+f"(c[2]), "+f"(c[3])
        : "r"(a[0]), "r"(a[1]), "r"(a[2]), "r"(a[3]), "r"(b0), "r"(b1));
}

__device__ __forceinline__ uint32_t swz(int row, int chunk) {
    return (uint32_t)(row * 128 + ((chunk ^ (row & 7)) << 4));
}

__global__ void __launch_bounds__(256, 2) gemm_qk(const float* __restrict__ bq,
                                                  int m_base)
{
    extern __shared__ char smem[];
    const uint32_t sbase = smem_to_u32(smem);
    const int tid = threadIdx.x;
    const int lane = tid & 31, wid = tid >> 5;
    const int wm = wid >> 2, wn = wid & 3;
    const int gid = lane >> 2, tig = lane & 3;

    const int n0 = blockIdx.x * BN;
    const int m0 = m_base + blockIdx.y * BM;
    const bool isq = (n0 < NQ_);
    const __half* wrow = g_wbuf + (size_t)n0 * DIN_;
    const __half* arow = g_hbuf + (size_t)m0 * DIN_;

    float acc[4][4][4];
#pragma unroll
    for (int a = 0; a < 4; a++)
#pragma unroll
        for (int b = 0; b < 4; b++)
#pragma unroll
            for (int c = 0; c < 4; c++) acc[a][b][c] = 0.f;

    const int arow_l   = wm * 64 + (lane & 15);
    const int achunk_l = lane >> 4;
    const int brow_l   = wn * 32 + (lane & 7) + ((lane & 16) >> 1);
    const int bchunk_l = (lane >> 3) & 1;

    auto load_stage = [&](int s) {
        const uint32_t slot = sbase + (uint32_t)(s % NSTAGE) * SLOT_BYTES;
        const int k0 = s * BK;
#pragma unroll
        for (int i = 0; i < 4; i++) {
            int id = tid + i * 256;
            int r = id >> 3, c = id & 7;
            cp16s(slot + swz(r, c), arow + (size_t)r * DIN_ + k0 + c * 8);
        }
#pragma unroll
        for (int i = 0; i < 4; i++) {
            int id = tid + i * 256;
            int r = id >> 3, c = id & 7;
            cp16s(slot + A_BYTES + swz(r, c), wrow + (size_t)r * DIN_ + k0 + c * 8);
        }
        asm volatile("cp.async.commit_group;\n");
    };

    load_stage(0);
    load_stage(1);

    const int NSTEPS = DIN_ / BK;  // 32
    for (int s = 0; s < NSTEPS; s++) {
        if (s < NSTEPS - 1) asm volatile("cp.async.wait_group 1;\n" ::: "memory");
        else                asm volatile("cp.async.wait_group 0;\n" ::: "memory");
        __syncthreads();

        const uint32_t slot = sbase + (uint32_t)(s % NSTAGE) * SLOT_BYTES;
#pragma unroll
        for (int ks = 0; ks < 4; ks++) {
            uint32_t af[4][4], bf[2][4];
#pragma unroll
            for (int tm = 0; tm < 4; tm++)
                ldsm_x4(af[tm][0], af[tm][1], af[tm][2], af[tm][3],
                        slot + swz(arow_l + tm * 16, 2 * ks + achunk_l));
#pragma unroll
            for (int np = 0; np < 2; np++)
                ldsm_x4(bf[np][0], bf[np][1], bf[np][2], bf[np][3],
                        slot + A_BYTES + swz(brow_l + np * 16, 2 * ks + bchunk_l));
#pragma unroll
            for (int tm = 0; tm < 4; tm++)
#pragma unroll
                for (int np = 0; np < 2; np++) {
                    mma_f16(acc[tm][2 * np],     af[tm], bf[np][0], bf[np][1]);
                    mma_f16(acc[tm][2 * np + 1], af[tm], bf[np][2], bf[np][3]);
                }
        }

        if (s + 2 < NSTEPS) load_stage(s + 2);
    }

    float bq0[4], bq1[4];
#pragma unroll
    for (int tn = 0; tn < 4; tn++) {
        int col = n0 + wn * 32 + tn * 8 + 2 * tig;
        bq0[tn] = isq ? __ldg(bq + col) : 0.f;
        bq1[tn] = isq ? __ldg(bq + col + 1) : 0.f;
    }
    __half* obase = isq ? g_qh : g_kh;
    const int ld = isq ? NQ_ : NK_;
    const int cb = isq ? n0 : (n0 - NQ_);

#pragma unroll
    for (int tm = 0; tm < 4; tm++) {
#pragma unroll
        for (int tn = 0; tn < 4; tn++) {
            int r = m0 + wm * 64 + tm * 16 + gid;
            int c = cb + wn * 32 + tn * 8 + 2 * tig;
            __half2 v0 = __floats2half2_rn(acc[tm][tn][0] + bq0[tn], acc[tm][tn][1] + bq1[tn]);
            __half2 v1 = __floats2half2_rn(acc[tm][tn][2] + bq0[tn], acc[tm][tn][3] + bq1[tn]);
            *reinterpret_cast<__half2*>(obase + (size_t)r * ld + c) = v0;
            *reinterpret_cast<__half2*>(obase + (size_t)(r + 8) * ld + c) = v1;
        }
    }
}

// ---------------------------------------------------------------------------
// Epilogue (R13 fp32 butterfly — proven best): token-pair ILP, dual fp32
// reduction chains, half2 kbq storage, 3-deep pair ring (61 KB).
// Micro-opts vs R13: __fdividef for the gate, precomputed 2*bb[g].
// ---------------------------------------------------------------------------
#define ETOK 32
#define EQB (NQ_ * 2)
#define EKB (NK_ * 2)
#define ETOKB (EQB + EKB)
#define EPSLOT (2 * ETOKB)
#define EPI_SMEM (3 * EPSLOT)          // 61440 B

__device__ __forceinline__ void wsum2(float& a, float& b) {
#pragma unroll
    for (int m = 16; m >= 1; m >>= 1) {
        a += __shfl_xor_sync(0xffffffffu, a, m);
        b += __shfl_xor_sync(0xffffffffu, b, m);
    }
}

__device__ __forceinline__ void ld4h_s(float o[4], uint32_t a) {
    uint32_t r0, r1;
    asm volatile("ld.shared.v2.b32 {%0,%1}, [%2];" : "=r"(r0), "=r"(r1) : "r"(a));
    __half2 h0 = *reinterpret_cast<__half2*>(&r0);
    __half2 h1 = *reinterpret_cast<__half2*>(&r1);
    float2 f0 = __half22float2(h0), f1 = __half22float2(h1);
    o[0] = f0.x; o[1] = f0.y; o[2] = f1.x; o[3] = f1.y;
}

__global__ void __launch_bounds__(256) epilogue_kernel(
    float* __restrict__ out, const float* __restrict__ bvec,
    const float* __restrict__ k_base, const float* __restrict__ qw,
    const float* __restrict__ kw, int nseq, int tok_base)
{
    extern __shared__ char esm[];
    const uint32_t sbase = smem_to_u32(esm);
    const int tid = threadIdx.x;
    const int lane = tid & 31;
    const int h = tid >> 5;
    const float inv_d = 0.08838834764831845f;
    const int tok0 = tok_base + blockIdx.x * ETOK;

    float qwr[4], kwr[4];
#pragma unroll
    for (int j = 0; j < 4; j++) {
        qwr[j] = qw[4 * lane + j];
        kwr[j] = kw[4 * lane + j];
    }
    __half2 kbq2[SINK_][2];
#pragma unroll
    for (int t = 0; t < SINK_; t++) {
        const float* kb = k_base + (size_t)(h * SINK_ + t) * DHEAD_ + 4 * lane;
        kbq2[t][0] = __floats2half2_rn(kb[0] * qwr[0], kb[1] * qwr[1]);
        kbq2[t][1] = __floats2half2_rn(kb[2] * qwr[2], kb[3] * qwr[3]);
    }

    float bb2[4];
#pragma unroll
    for (int g = 0; g < NGROUP_; g++) bb2[g] = 2.f * bvec[h * NGROUP_ + g];

    const bool up16 = (lane & 16) != 0;
    const bool up8  = (lane & 8) != 0;
    const bool up4  = (lane & 4) != 0;
    const bool up2  = (lane & 2) != 0;

    auto load_pair = [&](int p) {
        const uint32_t slot = sbase + (uint32_t)(p % 3) * EPSLOT;
#pragma unroll
        for (int tt = 0; tt < 2; tt++) {
            const int s = tok0 + 2 * p + tt;
            const uint32_t tb = slot + (uint32_t)tt * ETOKB;
            const __half* qsrc = g_qh + (size_t)s * NQ_;
            const __half* ksrc = g_kh + (size_t)s * NK_;
            cp16s(tb + (uint32_t)tid * 16, qsrc + tid * 8);
            cp16s(tb + (uint32_t)(tid + 256) * 16, qsrc + (tid + 256) * 8);
            if (tid < 128) cp16s(tb + EQB + (uint32_t)tid * 16, ksrc + tid * 8);
        }
        asm volatile("cp.async.commit_group;\n");
    };

    load_pair(0);
    load_pair(1);

    const int NPAIR = ETOK / 2;   // 16
    for (int p = 0; p < NPAIR; p++) {
        if (p < NPAIR - 1) asm volatile("cp.async.wait_group 1;\n" ::: "memory");
        else               asm volatile("cp.async.wait_group 0;\n" ::: "memory");
        __syncthreads();

        if (p + 2 < NPAIR) load_pair(p + 2);

        const uint32_t slot = sbase + (uint32_t)(p % 3) * EPSLOT;

        float kd[2][4], kdq[2][4], kss[2];
#pragma unroll
        for (int tt = 0; tt < 2; tt++) {
            ld4h_s(kd[tt], slot + (uint32_t)tt * ETOKB + EQB + (uint32_t)(h * DHEAD_ + 4 * lane) * 2);
            kss[tt] = kd[tt][0]*kd[tt][0] + kd[tt][1]*kd[tt][1]
                    + kd[tt][2]*kd[tt][2] + kd[tt][3]*kd[tt][3];
#pragma unroll
            for (int j = 0; j < 4; j++) kdq[tt][j] = kd[tt][j] * kwr[j] * qwr[j];
        }
        wsum2(kss[0], kss[1]);
        float rk[2];
#pragma unroll
        for (int tt = 0; tt < 2; tt++)
            rk[tt] = rsqrtf(kss[tt] * (1.0f / DHEAD_) + 1e-6f);

        float accg[2] = {0.f, 0.f};
#pragma unroll
        for (int g = 0; g < NGROUP_; g++) {
            float qd[2][4], qss[2], dtt[2];
#pragma unroll
            for (int tt = 0; tt < 2; tt++) {
                ld4h_s(qd[tt], slot + (uint32_t)tt * ETOKB
                       + (uint32_t)(h * (NGROUP_ * DHEAD_) + g * DHEAD_ + 4 * lane) * 2);
                qss[tt] = qd[tt][0]*qd[tt][0] + qd[tt][1]*qd[tt][1]
                        + qd[tt][2]*qd[tt][2] + qd[tt][3]*qd[tt][3];
                dtt[tt] = kdq[tt][0]*qd[tt][0] + kdq[tt][1]*qd[tt][1]
                        + kdq[tt][2]*qd[tt][2] + kdq[tt][3]*qd[tt][3];
            }

            float p2[2][SINK_];
#pragma unroll
            for (int t = 0; t < SINK_; t++) {
                float2 c0 = __half22float2(kbq2[t][0]);
                float2 c1 = __half22float2(kbq2[t][1]);
#pragma unroll
                for (int tt = 0; tt < 2; tt++)
                    p2[tt][t] = c0.x*qd[tt][0] + c0.y*qd[tt][1]
                              + c1.x*qd[tt][2] + c1.y*qd[tt][3];
            }

            wsum2(qss[0], qss[1]);
            wsum2(dtt[0], dtt[1]);

            float v8[2][8];
#pragma unroll
            for (int ii = 0; ii < 8; ii++)
#pragma unroll
                for (int tt = 0; tt < 2; tt++) {
                    float sd  = up16 ? p2[tt][ii] : p2[tt][8 + ii];
                    float kp2 = up16 ? p2[tt][8 + ii] : p2[tt][ii];
                    v8[tt][ii] = kp2 + __shfl_xor_sync(0xffffffffu, sd, 16);
                }
            float v4[2][4];
#pragma unroll
            for (int ii = 0; ii < 4; ii++)
#pragma unroll
                for (int tt = 0; tt < 2; tt++) {
                    float sd  = up8 ? v8[tt][ii] : v8[tt][4 + ii];
                    float kp2 = up8 ? v8[tt][4 + ii] : v8[tt][ii];
                    v4[tt][ii] = kp2 + __shfl_xor_sync(0xffffffffu, sd, 8);
                }
            float v2[2][2];
#pragma unroll
            for (int ii = 0; ii < 2; ii++)
#pragma unroll
                for (int tt = 0; tt < 2; tt++) {
                    float sd  = up4 ? v4[tt][ii] : v4[tt][2 + ii];
                    float kp2 = up4 ? v4[tt][2 + ii] : v4[tt][ii];
                    v2[tt][ii] = kp2 + __shfl_xor_sync(0xffffffffu, sd, 4);
                }
            float S[2], e[2];
#pragma unroll
            for (int tt = 0; tt < 2; tt++) {
                float sd1 = up2 ? v2[tt][0] : v2[tt][1];
                float kp1 = up2 ? v2[tt][1] : v2[tt][0];
                float v1 = kp1 + __shfl_xor_sync(0xffffffffu, sd1, 2);
                S[tt] = v1 + __shfl_xor_sync(0xffffffffu, v1, 1);
            }
#pragma unroll
            for (int tt = 0; tt < 2; tt++) {
                float rq = rsqrtf(qss[tt] * (1.0f / DHEAD_) + 1e-6f);
                float logit = rk[tt] * rq * dtt[tt] * inv_d + bb2[g];
                e[tt] = __expf(rq * S[tt] * inv_d - logit);
            }
            wsum2(e[0], e[1]);
#pragma unroll
            for (int tt = 0; tt < 2; tt++)
                accg[tt] += __fdividef(1.f, 1.f + 0.5f * e[tt]);
        }
        if (lane == 0) {
#pragma unroll
            for (int tt = 0; tt < 2; tt++)
                out[(size_t)h * nseq + tok0 + 2 * p + tt] = 0.25f * accg[tt];
        }
    }
}

// ---------------------------------------------------------------------------
// Launch: R13 topology (best measured) — equal chunks, single gemm stream,
// chunked hidden cvt on s2, epilogue chunks on high-priority s1.
// ---------------------------------------------------------------------------
extern "C" void kernel_launch(void* const* d_in, const int* in_sizes, int n_in,
                              void* d_out, int out_size)
{
    const float* hidden = (const float*)d_in[0];
    const float* Wq     = (const float*)d_in[1];
    const float* bq     = (const float*)d_in[2];
    const float* Wk     = (const float*)d_in[3];
    const float* qw     = (const float*)d_in[4];
    const float* kw     = (const float*)d_in[5];
    const float* bvec   = (const float*)d_in[6];
    const float* kbase  = (const float*)d_in[7];

    const int nseq = in_sizes[0] / DIN_;
    const int chunk = nseq / NCHUNK;

    static cudaStream_t s1 = nullptr, s2 = nullptr;
    static cudaEvent_t evRoot, evW, evE;
    static cudaEvent_t evG[NCHUNK], evC[NCHUNK];
    if (s1 == nullptr) {
        int lo, hi;
        cudaDeviceGetStreamPriorityRange(&lo, &hi);
        cudaStreamCreateWithPriority(&s1, cudaStreamNonBlocking, hi);
        cudaStreamCreateWithFlags(&s2, cudaStreamNonBlocking);
        cudaEventCreateWithFlags(&evRoot, cudaEventDisableTiming);
        cudaEventCreateWithFlags(&evW, cudaEventDisableTiming);
        cudaEventCreateWithFlags(&evE, cudaEventDisableTiming);
        for (int c = 0; c < NCHUNK; c++) {
            cudaEventCreateWithFlags(&evG[c], cudaEventDisableTiming);
            cudaEventCreateWithFlags(&evC[c], cudaEventDisableTiming);
        }
        cudaFuncSetAttribute(gemm_qk, cudaFuncAttributeMaxDynamicSharedMemorySize, SMEM_TOTAL);
        cudaFuncSetAttribute(epilogue_kernel, cudaFuncAttributeMaxDynamicSharedMemorySize, EPI_SMEM);
    }

    __half* hb;  cudaGetSymbolAddress((void**)&hb, g_hbuf);
    __half* wb;  cudaGetSymbolAddress((void**)&wb, g_wbuf);

    // fork
    cudaEventRecord(evRoot, 0);
    cudaStreamWaitEvent(s1, evRoot, 0);
    cudaStreamWaitEvent(s2, evRoot, 0);

    // s1: weight conversions
    {
        int n4 = NQ_ * DIN_ / 4;
        cvt_fp16<<<(n4 + 255) / 256, 256, 0, s1>>>((const float4*)Wq, (uint2*)wb, n4);
        n4 = NK_ * DIN_ / 4;
        cvt_fp16<<<(n4 + 255) / 256, 256, 0, s1>>>((const float4*)Wk,
                                                   (uint2*)(wb + (size_t)NQ_ * DIN_), n4);
        cudaEventRecord(evW, s1);
    }

    // s2: hidden conversion, chunk-wise
    {
        const int c4 = chunk * DIN_ / 4;
        for (int c = 0; c < NCHUNK; c++) {
            cvt_fp16<<<(c4 + 255) / 256, 256, 0, s2>>>(
                (const float4*)hidden + (size_t)c * c4,
                (uint2*)hb + (size_t)c * c4, c4);
            cudaEventRecord(evC[c], s2);
        }
    }

    // s0: gemm chunks; s1: epilogue chunks
    cudaStreamWaitEvent(0, evW, 0);
    dim3 ggrid(NTOT_ / BN, chunk / BM);   // 40 x 64 per chunk
    for (int c = 0; c < NCHUNK; c++) {
        cudaStreamWaitEvent(0, evC[c], 0);
        gemm_qk<<<ggrid, 256, SMEM_TOTAL>>>(bq, c * chunk);
        cudaEventRecord(evG[c], 0);
        cudaStreamWaitEvent(s1, evG[c], 0);
        epilogue_kernel<<<chunk / ETOK, 256, EPI_SMEM, s1>>>(
            (float*)d_out, bvec, kbase, qw, kw, nseq, c * chunk);
    }

    // join
    cudaEventRecord(evE, s1);
    cudaStreamWaitEvent(0, evE, 0);
}